// round 7
// baseline (speedup 1.0000x reference)
#include <cuda_runtime.h>
#include <math.h>
#include <stdint.h>

#define B_ 8
#define N_ 512
#define C_ 512
#define E_ 64
#define H_ 16
#define D_ 32
#define NEGBIG (-1e30f)
#define SCALE_ 0.17677669529663687f

typedef unsigned long long ull;

__device__ __forceinline__ ull pk2(float lo, float hi) {
    ull r; asm("mov.b64 %0,{%1,%2};" : "=l"(r) : "f"(lo), "f"(hi)); return r;
}
__device__ __forceinline__ void upk2(ull v, float& lo, float& hi) {
    asm("mov.b64 {%0,%1},%2;" : "=f"(lo), "=f"(hi) : "l"(v));
}
__device__ __forceinline__ ull ffma2(ull a, ull b, ull c) {
    ull d; asm("fma.rn.f32x2 %0,%1,%2,%3;" : "=l"(d) : "l"(a), "l"(b), "l"(c)); return d;
}
__device__ __forceinline__ ull fadd2(ull a, ull b) {
    ull d; asm("add.rn.f32x2 %0,%1,%2;" : "=l"(d) : "l"(a), "l"(b)); return d;
}

__device__ float g_q  [B_*H_*N_*D_];
__device__ float g_kT [B_*H_*D_*N_];
__device__ float g_v  [B_*H_*N_*D_];
__device__ float g_nodep[B_*N_*C_];
__device__ float g_w  [B_*N_*E_];
__device__ float g_pfc[C_*E_];
__device__ float g_pbias[C_];

// ---------------- Kernel 1: QKV GEMM + scatter ----------------
__global__ __launch_bounds__(256, 2)
void qkv_gemm_kernel(const float* __restrict__ A, const float* __restrict__ Wt,
                     const float* __restrict__ bias)
{
    __shared__ float As[8][132];
    __shared__ float Bs[8][132];
    const int tid = threadIdx.x;
    const int tx = tid & 15, ty = tid >> 4;
    const int row0 = blockIdx.y * 128, col0 = blockIdx.x * 128;
    const int lr = tid >> 1;
    const int lk = (tid & 1) * 4;

    float acc[8][8];
#pragma unroll
    for (int i = 0; i < 8; i++)
#pragma unroll
        for (int j = 0; j < 8; j++) acc[i][j] = 0.f;

    for (int k0 = 0; k0 < 512; k0 += 8) {
        float4 a4 = *(const float4*)(A  + (size_t)(row0 + lr) * 512 + k0 + lk);
        float4 b4 = *(const float4*)(Wt + (size_t)(col0 + lr) * 512 + k0 + lk);
        As[lk+0][lr]=a4.x; As[lk+1][lr]=a4.y; As[lk+2][lr]=a4.z; As[lk+3][lr]=a4.w;
        Bs[lk+0][lr]=b4.x; Bs[lk+1][lr]=b4.y; Bs[lk+2][lr]=b4.z; Bs[lk+3][lr]=b4.w;
        __syncthreads();
#pragma unroll
        for (int kk = 0; kk < 8; kk++) {
            float ar[8], br[8];
            *(float4*)(ar)   = *(const float4*)&As[kk][ty*8];
            *(float4*)(ar+4) = *(const float4*)&As[kk][ty*8+4];
            *(float4*)(br)   = *(const float4*)&Bs[kk][tx*8];
            *(float4*)(br+4) = *(const float4*)&Bs[kk][tx*8+4];
#pragma unroll
            for (int i = 0; i < 8; i++)
#pragma unroll
                for (int j = 0; j < 8; j++) acc[i][j] += ar[i] * br[j];
        }
        __syncthreads();
    }

#pragma unroll
    for (int i = 0; i < 8; i++) {
        const int r = row0 + ty * 8 + i;
        const int b = r >> 9, n = r & 511;
#pragma unroll
        for (int j = 0; j < 8; j++) {
            const int c = col0 + tx * 8 + j;
            const float v = acc[i][j] + bias[c];
            const int three = c >> 9, h = (c >> 5) & 15, d = c & 31;
            if (three == 0)      g_q [((b*H_+h)*N_+n)*D_ + d] = v;
            else if (three == 1) g_kT[((b*H_+h)*D_+d)*N_ + n] = v;
            else                 g_v [((b*H_+h)*N_+n)*D_ + d] = v;
        }
    }
}

// ---------------- Kernel 2: fold fc into proj ----------------
__global__ void pfc_kernel(const float* __restrict__ proj_w,
                           const float* __restrict__ fc_w,
                           const float* __restrict__ fc_b,
                           const float* __restrict__ proj_b)
{
    const int c = blockIdx.x;
    const int e = threadIdx.x;  // 64
    const float* pr = proj_w + (size_t)c * 512;
    float acc = 0.f;
#pragma unroll 4
    for (int j = 0; j < 512; j++) acc += pr[j] * fc_w[j * 64 + e];
    g_pfc[c * 64 + e] = acc;

    float pb = 0.f;
    for (int j = e; j < 512; j += 64) pb += pr[j] * fc_b[j];
    __shared__ float red[64];
    red[e] = pb;
    __syncthreads();
    if (e == 0) {
        float s = proj_b[c];
#pragma unroll
        for (int i = 0; i < 64; i++) s += red[i];
        g_pbias[c] = s;
    }
}

// ---------------- Kernel 3: fused attention + edge update (unchanged R4 candidate) ----------------
#define SMEM_FLOATS (32768 + 2048 + 2048 + 2048 + 2048 + 128 + 512 + 64 + 16)

__global__ __launch_bounds__(512, 1)
void fused_attn_kernel(const float* __restrict__ edge,
                       const unsigned char* __restrict__ mask,
                       const float* __restrict__ reduce_w,
                       const float* __restrict__ reduce_b,
                       const float* __restrict__ expand_w,
                       const float* __restrict__ expand_b,
                       float* __restrict__ edge_out)
{
    extern __shared__ float sm[];
    float* sS   = sm;                  // [4][16][512]
    float* sQ   = sS + 32768;          // [h][d][r]
    float* sAb  = sQ + 2048;           // [h][mm][r]
    ull*   sRW2 = (ull*)(sAb + 2048);  // [h][e] dup-packed
    ull*   sEW2 = sRW2 + 1024;         // [e][h] dup-packed
    ull*   sEB2 = sEW2 + 1024;         // [e] dup-packed
    float* sNeg = (float*)(sEB2 + 64); // [512]
    float* sIv  = sNeg + 512;          // [4][16]
    float* sRB  = sIv + 64;            // [16]

    const int tid  = threadIdx.x;
    const int w    = tid >> 5;
    const int lane = tid & 31;
    const int b    = blockIdx.y;
    const int n0   = blockIdx.x * 4;

    for (int i = tid; i < 1024; i += 512) {
        const float rw = reduce_w[i];
        sRW2[i] = pk2(rw, rw);
        const float ew = expand_w[i];
        sEW2[i] = pk2(ew, ew);
    }
    sNeg[tid] = mask[b * N_ + tid] ? NEGBIG : 0.f;
    if (tid < 16) sRB[tid] = reduce_b[tid];
    if (tid < 64) { const float eb = expand_b[tid]; sEB2[tid] = pk2(eb, eb); }
    for (int i = tid; i < 2048; i += 512) {
        const int r = i & 3, d = (i >> 2) & 31, h = i >> 7;
        sQ[i] = g_q[((b*H_+h)*N_ + (n0+r))*D_ + d];
    }
    __syncthreads();

    // P1: edge bias (f32x2)
    {
        const int r = w >> 2;
        const int mBase = (w & 3) * 128 + lane;
        ull acc01[16], acc23[16];
#pragma unroll
        for (int h = 0; h < 16; h++) {
            const ull rb2 = pk2(sRB[h], sRB[h]);
            acc01[h] = rb2; acc23[h] = rb2;
        }
        const float* ep = edge + (size_t)b*E_*N_*N_ + (size_t)(n0+r)*N_ + mBase;
#pragma unroll 4
        for (int e = 0; e < 64; e++) {
            const float* epe = ep + (size_t)e*N_*N_;
            const ull ev01 = pk2(epe[0],  epe[32]);
            const ull ev23 = pk2(epe[64], epe[96]);
            const ull* rwp = sRW2 + e;
#pragma unroll
            for (int h = 0; h < 16; h++) {
                const ull rw2 = rwp[h*64];
                acc01[h] = ffma2(ev01, rw2, acc01[h]);
                acc23[h] = ffma2(ev23, rw2, acc23[h]);
            }
        }
#pragma unroll
        for (int h = 0; h < 16; h++) {
            float v0, v1, v2, v3;
            upk2(acc01[h], v0, v1);
            upk2(acc23[h], v2, v3);
            float* sp = sS + (r*16+h)*512 + mBase;
            sp[0] = v0; sp[32] = v1; sp[64] = v2; sp[96] = v3;
        }
    }
    __syncthreads();

    // P2: s += SCALE * q.kT
    {
        const int h = w;
        const float* kp = g_kT + ((size_t)b*H_ + h)*D_*N_;
        const float* qp = sQ + h*128;
        for (int j = 0; j < 16; j++) {
            const int m = j*32 + lane;
            float a0=0.f, a1=0.f, a2=0.f, a3=0.f;
#pragma unroll 8
            for (int d = 0; d < 32; d++) {
                const float kv = kp[(size_t)d*N_ + m];
                const float4 q4 = *(const float4*)(qp + d*4);
                a0 += q4.x*kv; a1 += q4.y*kv; a2 += q4.z*kv; a3 += q4.w*kv;
            }
            sS[(0*16+h)*512+m] += a0*SCALE_;
            sS[(1*16+h)*512+m] += a1*SCALE_;
            sS[(2*16+h)*512+m] += a2*SCALE_;
            sS[(3*16+h)*512+m] += a3*SCALE_;
        }
    }
    __syncthreads();

    // P3: softmax denominators (no max shift; scores O(1))
    {
        const int p0 = w * 4;
#pragma unroll
        for (int pi = 0; pi < 4; pi++) {
            const int p = p0 + pi, pr = p >> 4, ph = p & 15;
            const float* sp = sS + (pr*16+ph)*512;
            float sum = 0.f;
#pragma unroll 4
            for (int j = 0; j < 16; j++) { const int m=j*32+lane; sum += __expf(sp[m]+sNeg[m]); }
            for (int off = 16; off; off >>= 1) sum += __shfl_xor_sync(0xffffffffu, sum, off);
            if (lane == 0) sIv[pr*16+ph] = 1.f/sum;
        }
    }
    __syncthreads();

    // P4: nodep = a @ v
    {
        const int h = w;
        const float* vp = g_v + ((size_t)b*H_ + h)*N_*D_;
        const float iv0=sIv[0*16+h], iv1=sIv[1*16+h];
        const float iv2=sIv[2*16+h], iv3=sIv[3*16+h];
        float acc0=0.f, acc1=0.f, acc2=0.f, acc3=0.f;
        float* ab = sAb + h*128;
        for (int j = 0; j < 16; j++) {
            const int m = j*32 + lane;
            const float neg = sNeg[m];
            float4 av;
            av.x = __expf(sS[(0*16+h)*512+m]+neg)*iv0;
            av.y = __expf(sS[(1*16+h)*512+m]+neg)*iv1;
            av.z = __expf(sS[(2*16+h)*512+m]+neg)*iv2;
            av.w = __expf(sS[(3*16+h)*512+m]+neg)*iv3;
            __syncwarp();
            *(float4*)(ab + lane*4) = av;
            __syncwarp();
#pragma unroll 8
            for (int mm = 0; mm < 32; mm++) {
                const float vv = vp[(size_t)(j*32+mm)*D_ + lane];
                const float4 a4 = *(const float4*)(ab + mm*4);
                acc0 += a4.x*vv; acc1 += a4.y*vv; acc2 += a4.z*vv; acc3 += a4.w*vv;
            }
        }
        g_nodep[((size_t)b*N_ + n0+0)*C_ + h*32 + lane] = acc0;
        g_nodep[((size_t)b*N_ + n0+1)*C_ + h*32 + lane] = acc1;
        g_nodep[((size_t)b*N_ + n0+2)*C_ + h*32 + lane] = acc2;
        g_nodep[((size_t)b*N_ + n0+3)*C_ + h*32 + lane] = acc3;
    }

    // P5: edge_out + softmax-weighted sum (f32x2)
    {
        const int r  = w >> 2;
        const int e0 = (w & 3) * 16;
        float* eoBase = edge_out + (size_t)b*E_*N_*N_ + (size_t)(n0+r)*N_;
        const float* sSr = sS + r*16*512;
        const float* ivp = sIv + r*16;

        for (int half = 0; half < 2; half++) {
            ull S2[8], W2[8];
#pragma unroll
            for (int q = 0; q < 8; q++) { S2[q] = 0ull; W2[q] = 0ull; }

            for (int j = 0; j < 8; j++) {
                const int m0 = j*64 + lane, m1 = m0 + 32;
                const float neg0 = sNeg[m0], neg1 = sNeg[m1];
                ull t2[16];
#pragma unroll
                for (int h = 0; h < 16; h++) {
                    const float iv = ivp[h];
                    const float s0 = sSr[h*512+m0], s1 = sSr[h*512+m1];
                    const float t0 = __expf(s0+neg0)*iv + s0;
                    const float t1 = __expf(s1+neg1)*iv + s1;
                    t2[h] = pk2(t0, t1);
                }
#pragma unroll
                for (int q = 0; q < 8; q++) {
                    const int e = e0 + half*8 + q;
                    ull a2 = sEB2[e];
                    const ull* ewp = sEW2 + e*16;
#pragma unroll
                    for (int h = 0; h < 16; h++)
                        a2 = ffma2(t2[h], ewp[h], a2);
                    float a0, a1;
                    upk2(a2, a0, a1);
                    eoBase[(size_t)e*N_*N_ + m0] = a0;
                    eoBase[(size_t)e*N_*N_ + m1] = a1;
                    const float p0 = __expf(a0 + neg0), p1 = __expf(a1 + neg1);
                    const ull p2 = pk2(p0, p1);
                    S2[q] = fadd2(S2[q], p2);
                    W2[q] = ffma2(p2, a2, W2[q]);
                }
            }
#pragma unroll
            for (int q = 0; q < 8; q++) {
                float sl, sh, wl, wh;
                upk2(S2[q], sl, sh); upk2(W2[q], wl, wh);
                float S_ = sl + sh, W_ = wl + wh;
                for (int off = 16; off; off >>= 1) {
                    S_ += __shfl_xor_sync(0xffffffffu, S_, off);
                    W_ += __shfl_xor_sync(0xffffffffu, W_, off);
                }
                if (lane == 0)
                    g_w[((size_t)b*N_ + n0+r)*E_ + e0 + half*8 + q] = W_/S_;
            }
        }
    }
}

// ---------------- Kernel 4: out = nodep@proj^T + w@pfc^T + pbias ----------------
// Retiled 64x128 (grid 4x64 = 256 CTAs) for full-wave occupancy.
__global__ __launch_bounds__(256, 2)
void out_gemm_kernel(const float* __restrict__ proj_w, float* __restrict__ out)
{
    __shared__ float As[8][68];
    __shared__ float Bs[8][132];
    const int tid = threadIdx.x;
    const int tx = tid & 15, ty = tid >> 4;
    const int row0 = blockIdx.y * 64, col0 = blockIdx.x * 128;
    const int lrA = tid >> 2, lkA = (tid & 3) * 2;
    const int lrB = tid >> 1, lkB = (tid & 1) * 4;

    float acc[4][8];
#pragma unroll
    for (int i = 0; i < 4; i++)
#pragma unroll
        for (int j = 0; j < 8; j++) acc[i][j] = 0.f;

    for (int k0 = 0; k0 < 512; k0 += 8) {
        float2 a2 = *(const float2*)(g_nodep + (size_t)(row0+lrA)*512 + k0+lkA);
        float4 b4 = *(const float4*)(proj_w  + (size_t)(col0+lrB)*512 + k0+lkB);
        As[lkA+0][lrA]=a2.x; As[lkA+1][lrA]=a2.y;
        Bs[lkB+0][lrB]=b4.x; Bs[lkB+1][lrB]=b4.y; Bs[lkB+2][lrB]=b4.z; Bs[lkB+3][lrB]=b4.w;
        __syncthreads();
#pragma unroll
        for (int kk = 0; kk < 8; kk++) {
            float ar[4], br[8];
            *(float4*)(ar)   = *(const float4*)&As[kk][ty*4];
            *(float4*)(br)   = *(const float4*)&Bs[kk][tx*8];
            *(float4*)(br+4) = *(const float4*)&Bs[kk][tx*8+4];
#pragma unroll
            for (int i = 0; i < 4; i++)
#pragma unroll
                for (int j = 0; j < 8; j++) acc[i][j] += ar[i]*br[j];
        }
        __syncthreads();
    }
    // K tail: w @ pfc^T
    for (int k0 = 0; k0 < 64; k0 += 8) {
        float2 a2 = *(const float2*)(g_w   + (size_t)(row0+lrA)*64 + k0+lkA);
        float4 b4 = *(const float4*)(g_pfc + (size_t)(col0+lrB)*64 + k0+lkB);
        As[lkA+0][lrA]=a2.x; As[lkA+1][lrA]=a2.y;
        Bs[lkB+0][lrB]=b4.x; Bs[lkB+1][lrB]=b4.y; Bs[lkB+2][lrB]=b4.z; Bs[lkB+3][lrB]=b4.w;
        __syncthreads();
#pragma unroll
        for (int kk = 0; kk < 8; kk++) {
            float ar[4], br[8];
            *(float4*)(ar)   = *(const float4*)&As[kk][ty*4];
            *(float4*)(br)   = *(const float4*)&Bs[kk][tx*8];
            *(float4*)(br+4) = *(const float4*)&Bs[kk][tx*8+4];
#pragma unroll
            for (int i = 0; i < 4; i++)
#pragma unroll
                for (int j = 0; j < 8; j++) acc[i][j] += ar[i]*br[j];
        }
        __syncthreads();
    }

#pragma unroll
    for (int i = 0; i < 4; i++) {
        const int r = row0 + ty*4 + i;
#pragma unroll
        for (int j = 0; j < 8; j++) {
            const int c = col0 + tx*8 + j;
            out[(size_t)r*512 + c] = acc[i][j] + g_pbias[c];
        }
    }
}

extern "C" void kernel_launch(void* const* d_in, const int* in_sizes, int n_in,
                              void* d_out, int out_size)
{
    const float* node   = (const float*)d_in[0];
    const float* edge   = (const float*)d_in[1];
    const unsigned char* mask = (const unsigned char*)d_in[2];
    const float* qkv_w  = (const float*)d_in[3];
    const float* qkv_b  = (const float*)d_in[4];
    const float* red_w  = (const float*)d_in[5];
    const float* red_b  = (const float*)d_in[6];
    const float* exp_w  = (const float*)d_in[7];
    const float* exp_b  = (const float*)d_in[8];
    const float* fc_w   = (const float*)d_in[9];
    const float* fc_b   = (const float*)d_in[10];
    const float* proj_w = (const float*)d_in[11];
    const float* proj_b = (const float*)d_in[12];

    float* node_out = (float*)d_out;
    float* edge_out = (float*)d_out + (size_t)B_*N_*C_;

    qkv_gemm_kernel<<<dim3(12, 32), 256>>>(node, qkv_w, qkv_b);
    pfc_kernel<<<512, 64>>>(proj_w, fc_w, fc_b, proj_b);

    const int smemB = SMEM_FLOATS * 4;
    cudaFuncSetAttribute(fused_attn_kernel, cudaFuncAttributeMaxDynamicSharedMemorySize, smemB);
    fused_attn_kernel<<<dim3(N_/4, B_), 512, smemB>>>(edge, mask, red_w, red_b,
                                                      exp_w, exp_b, edge_out);

    out_gemm_kernel<<<dim3(4, 64), 256>>>(proj_w, node_out);
}

// round 13
// speedup vs baseline: 1.2589x; 1.2589x over previous
#include <cuda_runtime.h>
#include <math.h>
#include <stdint.h>

#define B_ 8
#define N_ 512
#define C_ 512
#define E_ 64
#define H_ 16
#define D_ 32
#define NEGBIG (-1e30f)
#define SCALE_ 0.17677669529663687f

__device__ float g_q  [B_*H_*N_*D_];
__device__ float g_kT [B_*H_*D_*N_];
__device__ float g_v  [B_*H_*N_*D_];
__device__ float g_nodep[B_*N_*C_];
__device__ float g_w  [B_*N_*E_];
__device__ float g_pfc[C_*E_];
__device__ float g_pbias[C_];

// ---------------- Kernel 1: QKV GEMM + scatter ----------------
__global__ __launch_bounds__(256, 2)
void qkv_gemm_kernel(const float* __restrict__ A, const float* __restrict__ Wt,
                     const float* __restrict__ bias)
{
    __shared__ float As[8][132];
    __shared__ float Bs[8][132];
    const int tid = threadIdx.x;
    const int tx = tid & 15, ty = tid >> 4;
    const int row0 = blockIdx.y * 128, col0 = blockIdx.x * 128;
    const int lr = tid >> 1;
    const int lk = (tid & 1) * 4;

    float acc[8][8];
#pragma unroll
    for (int i = 0; i < 8; i++)
#pragma unroll
        for (int j = 0; j < 8; j++) acc[i][j] = 0.f;

    for (int k0 = 0; k0 < 512; k0 += 8) {
        float4 a4 = *(const float4*)(A  + (size_t)(row0 + lr) * 512 + k0 + lk);
        float4 b4 = *(const float4*)(Wt + (size_t)(col0 + lr) * 512 + k0 + lk);
        As[lk+0][lr]=a4.x; As[lk+1][lr]=a4.y; As[lk+2][lr]=a4.z; As[lk+3][lr]=a4.w;
        Bs[lk+0][lr]=b4.x; Bs[lk+1][lr]=b4.y; Bs[lk+2][lr]=b4.z; Bs[lk+3][lr]=b4.w;
        __syncthreads();
#pragma unroll
        for (int kk = 0; kk < 8; kk++) {
            float ar[8], br[8];
            *(float4*)(ar)   = *(const float4*)&As[kk][ty*8];
            *(float4*)(ar+4) = *(const float4*)&As[kk][ty*8+4];
            *(float4*)(br)   = *(const float4*)&Bs[kk][tx*8];
            *(float4*)(br+4) = *(const float4*)&Bs[kk][tx*8+4];
#pragma unroll
            for (int i = 0; i < 8; i++)
#pragma unroll
                for (int j = 0; j < 8; j++) acc[i][j] += ar[i] * br[j];
        }
        __syncthreads();
    }

#pragma unroll
    for (int i = 0; i < 8; i++) {
        const int r = row0 + ty * 8 + i;
        const int b = r >> 9, n = r & 511;
#pragma unroll
        for (int j = 0; j < 8; j++) {
            const int c = col0 + tx * 8 + j;
            const float v = acc[i][j] + bias[c];
            const int three = c >> 9, h = (c >> 5) & 15, d = c & 31;
            if (three == 0)      g_q [((b*H_+h)*N_+n)*D_ + d] = v;
            else if (three == 1) g_kT[((b*H_+h)*D_+d)*N_ + n] = v;
            else                 g_v [((b*H_+h)*N_+n)*D_ + d] = v;
        }
    }
}

// ---------------- Kernel 2: fold fc into proj ----------------
__global__ void pfc_kernel(const float* __restrict__ proj_w,
                           const float* __restrict__ fc_w,
                           const float* __restrict__ fc_b,
                           const float* __restrict__ proj_b)
{
    const int c = blockIdx.x;
    const int e = threadIdx.x;  // 64
    const float* pr = proj_w + (size_t)c * 512;
    float acc = 0.f;
#pragma unroll 4
    for (int j = 0; j < 512; j++) acc += pr[j] * fc_w[j * 64 + e];
    g_pfc[c * 64 + e] = acc;

    float pb = 0.f;
    for (int j = e; j < 512; j += 64) pb += pr[j] * fc_b[j];
    __shared__ float red[64];
    red[e] = pb;
    __syncthreads();
    if (e == 0) {
        float s = proj_b[c];
#pragma unroll
        for (int i = 0; i < 64; i++) s += red[i];
        g_pbias[c] = s;
    }
}

// ---------------- Kernel 3: fused attention + edge update ----------------
// R3 scalar base + (a) max-free softmax, (b) P1 e-loop unroll 4.
#define SMEM_FLOATS (32768 + 2048 + 2048 + 1024 + 1024 + 512 + 64 + 16 + 64)

__global__ __launch_bounds__(512, 1)
void fused_attn_kernel(const float* __restrict__ edge,
                       const unsigned char* __restrict__ mask,
                       const float* __restrict__ reduce_w,
                       const float* __restrict__ reduce_b,
                       const float* __restrict__ expand_w,
                       const float* __restrict__ expand_b,
                       float* __restrict__ edge_out)
{
    extern __shared__ float sm[];
    float* sS   = sm;                 // [4][16][512]
    float* sQ   = sS + 32768;         // [h][d][r]
    float* sAb  = sQ + 2048;          // [h][mm][r]
    float* sRW  = sAb + 2048;         // [16][64]
    float* sEW  = sRW + 1024;         // [64][16]
    float* sNeg = sEW + 1024;         // [512]
    float* sIv  = sNeg + 512;         // [4][16]
    float* sRB  = sIv + 64;           // [16]
    float* sEB  = sRB + 16;           // [64]

    const int tid  = threadIdx.x;
    const int w    = tid >> 5;
    const int lane = tid & 31;
    const int b    = blockIdx.y;
    const int n0   = blockIdx.x * 4;

    for (int i = tid; i < 1024; i += 512) { sRW[i] = reduce_w[i]; sEW[i] = expand_w[i]; }
    sNeg[tid] = mask[b * N_ + tid] ? NEGBIG : 0.f;
    if (tid < 16) sRB[tid] = reduce_b[tid];
    if (tid < 64) sEB[tid] = expand_b[tid];
    for (int i = tid; i < 2048; i += 512) {
        const int r = i & 3, d = (i >> 2) & 31, h = i >> 7;
        sQ[i] = g_q[((b*H_+h)*N_ + (n0+r))*D_ + d];
    }
    __syncthreads();

    // P1: edge bias (scalar, unroll 4 for MLP)
    {
        const int r = w >> 2;
        const int mBase = (w & 3) * 128 + lane;
        float acc[16][4];
#pragma unroll
        for (int h = 0; h < 16; h++) {
            const float rb = sRB[h];
#pragma unroll
            for (int jj = 0; jj < 4; jj++) acc[h][jj] = rb;
        }
        const float* ep = edge + (size_t)b*E_*N_*N_ + (size_t)(n0+r)*N_ + mBase;
#pragma unroll 4
        for (int e = 0; e < 64; e++) {
            const float* epe = ep + (size_t)e*N_*N_;
            const float ev0 = epe[0], ev1 = epe[32], ev2 = epe[64], ev3 = epe[96];
#pragma unroll
            for (int h = 0; h < 16; h++) {
                const float rw = sRW[h*64 + e];
                acc[h][0] += ev0*rw; acc[h][1] += ev1*rw;
                acc[h][2] += ev2*rw; acc[h][3] += ev3*rw;
            }
        }
#pragma unroll
        for (int h = 0; h < 16; h++)
#pragma unroll
            for (int jj = 0; jj < 4; jj++)
                sS[(r*16+h)*512 + mBase + jj*32] = acc[h][jj];
    }
    __syncthreads();

    // P2: s += SCALE * q.kT (warp = head)
    {
        const int h = w;
        const float* kp = g_kT + ((size_t)b*H_ + h)*D_*N_;
        const float* qp = sQ + h*128;
        for (int j = 0; j < 16; j++) {
            const int m = j*32 + lane;
            float a0=0.f, a1=0.f, a2=0.f, a3=0.f;
#pragma unroll 8
            for (int d = 0; d < 32; d++) {
                const float kv = kp[(size_t)d*N_ + m];
                const float4 q4 = *(const float4*)(qp + d*4);
                a0 += q4.x*kv; a1 += q4.y*kv; a2 += q4.z*kv; a3 += q4.w*kv;
            }
            sS[(0*16+h)*512+m] += a0*SCALE_;
            sS[(1*16+h)*512+m] += a1*SCALE_;
            sS[(2*16+h)*512+m] += a2*SCALE_;
            sS[(3*16+h)*512+m] += a3*SCALE_;
        }
    }
    __syncthreads();

    // P3: softmax denominators only (max-free; scores O(1))
    {
        const int p0 = w * 4;
#pragma unroll
        for (int pi = 0; pi < 4; pi++) {
            const int p = p0 + pi, pr = p >> 4, ph = p & 15;
            const float* sp = sS + (pr*16+ph)*512;
            float sum = 0.f;
#pragma unroll 4
            for (int j = 0; j < 16; j++) { const int m=j*32+lane; sum += __expf(sp[m]+sNeg[m]); }
            for (int off = 16; off; off >>= 1) sum += __shfl_xor_sync(0xffffffffu, sum, off);
            if (lane == 0) sIv[pr*16+ph] = 1.f/sum;
        }
    }
    __syncthreads();

    // P4: nodep = a @ v (warp = head, lane = d)
    {
        const int h = w;
        const float* vp = g_v + ((size_t)b*H_ + h)*N_*D_;
        const float iv0=sIv[0*16+h], iv1=sIv[1*16+h];
        const float iv2=sIv[2*16+h], iv3=sIv[3*16+h];
        float acc0=0.f, acc1=0.f, acc2=0.f, acc3=0.f;
        float* ab = sAb + h*128;
        for (int j = 0; j < 16; j++) {
            const int m = j*32 + lane;
            const float neg = sNeg[m];
            float4 av;
            av.x = __expf(sS[(0*16+h)*512+m]+neg)*iv0;
            av.y = __expf(sS[(1*16+h)*512+m]+neg)*iv1;
            av.z = __expf(sS[(2*16+h)*512+m]+neg)*iv2;
            av.w = __expf(sS[(3*16+h)*512+m]+neg)*iv3;
            __syncwarp();
            *(float4*)(ab + lane*4) = av;
            __syncwarp();
#pragma unroll 8
            for (int mm = 0; mm < 32; mm++) {
                const float vv = vp[(size_t)(j*32+mm)*D_ + lane];
                const float4 a4 = *(const float4*)(ab + mm*4);
                acc0 += a4.x*vv; acc1 += a4.y*vv; acc2 += a4.z*vv; acc3 += a4.w*vv;
            }
        }
        g_nodep[((size_t)b*N_ + n0+0)*C_ + h*32 + lane] = acc0;
        g_nodep[((size_t)b*N_ + n0+1)*C_ + h*32 + lane] = acc1;
        g_nodep[((size_t)b*N_ + n0+2)*C_ + h*32 + lane] = acc2;
        g_nodep[((size_t)b*N_ + n0+3)*C_ + h*32 + lane] = acc3;
    }
    // sS/sIv read-only below; ordered by P3's barrier.

    // P5: edge_out + softmax-weighted sum (scalar, fixed shift)
    {
        const int r  = w >> 2;
        const int e0 = (w & 3) * 16;
        float* eoBase = edge_out + (size_t)b*E_*N_*N_ + (size_t)(n0+r)*N_;
        const float* sSr = sS + r*16*512;
        const float* ivp = sIv + r*16;

        for (int half = 0; half < 2; half++) {
            float S[8], W8[8];
#pragma unroll
            for (int q = 0; q < 8; q++) { S[q]=0.f; W8[q]=0.f; }

            for (int j = 0; j < 8; j++) {
                const int m0 = j*64 + lane, m1 = m0 + 32;
                const float neg0 = sNeg[m0], neg1 = sNeg[m1];
                float t0[16], t1[16];
#pragma unroll
                for (int h = 0; h < 16; h++) {
                    const float iv = ivp[h];
                    const float s0 = sSr[h*512+m0], s1 = sSr[h*512+m1];
                    t0[h] = __expf(s0+neg0)*iv + s0;
                    t1[h] = __expf(s1+neg1)*iv + s1;
                }
#pragma unroll
                for (int q = 0; q < 8; q++) {
                    const int e = e0 + half*8 + q;
                    float a0 = sEB[e], a1 = a0;
#pragma unroll
                    for (int h = 0; h < 16; h++) {
                        const float ew = sEW[e*16+h];
                        a0 += t0[h]*ew; a1 += t1[h]*ew;
                    }
                    eoBase[(size_t)e*N_*N_ + m0] = a0;
                    eoBase[(size_t)e*N_*N_ + m1] = a1;
                    const float p0 = __expf(a0 + neg0), p1 = __expf(a1 + neg1);
                    S[q]  += p0 + p1;
                    W8[q] += p0*a0 + p1*a1;
                }
            }
#pragma unroll
            for (int q = 0; q < 8; q++) {
                float S_ = S[q], W_ = W8[q];
                for (int off = 16; off; off >>= 1) {
                    S_ += __shfl_xor_sync(0xffffffffu, S_, off);
                    W_ += __shfl_xor_sync(0xffffffffu, W_, off);
                }
                if (lane == 0)
                    g_w[((size_t)b*N_ + n0+r)*E_ + e0 + half*8 + q] = W_/S_;
            }
        }
    }
}

// ---------------- Kernel 4: out = nodep@proj^T + w@pfc^T + pbias (R3 128x128) ----------------
__global__ __launch_bounds__(256, 2)
void out_gemm_kernel(const float* __restrict__ proj_w, float* __restrict__ out)
{
    __shared__ float As[8][132];
    __shared__ float Bs[8][132];
    const int tid = threadIdx.x;
    const int tx = tid & 15, ty = tid >> 4;
    const int row0 = blockIdx.y * 128, col0 = blockIdx.x * 128;
    const int lr = tid >> 1;
    const int lk = (tid & 1) * 4;

    float acc[8][8];
#pragma unroll
    for (int i = 0; i < 8; i++)
#pragma unroll
        for (int j = 0; j < 8; j++) acc[i][j] = 0.f;

    for (int k0 = 0; k0 < 512; k0 += 8) {
        float4 a4 = *(const float4*)(g_nodep + (size_t)(row0+lr)*512 + k0+lk);
        float4 b4 = *(const float4*)(proj_w  + (size_t)(col0+lr)*512 + k0+lk);
        As[lk+0][lr]=a4.x; As[lk+1][lr]=a4.y; As[lk+2][lr]=a4.z; As[lk+3][lr]=a4.w;
        Bs[lk+0][lr]=b4.x; Bs[lk+1][lr]=b4.y; Bs[lk+2][lr]=b4.z; Bs[lk+3][lr]=b4.w;
        __syncthreads();
#pragma unroll
        for (int kk = 0; kk < 8; kk++) {
            float ar[8], br[8];
            *(float4*)(ar)   = *(const float4*)&As[kk][ty*8];
            *(float4*)(ar+4) = *(const float4*)&As[kk][ty*8+4];
            *(float4*)(br)   = *(const float4*)&Bs[kk][tx*8];
            *(float4*)(br+4) = *(const float4*)&Bs[kk][tx*8+4];
#pragma unroll
            for (int i = 0; i < 8; i++)
#pragma unroll
                for (int j = 0; j < 8; j++) acc[i][j] += ar[i]*br[j];
        }
        __syncthreads();
    }
    for (int k0 = 0; k0 < 64; k0 += 8) {
        float4 a4 = *(const float4*)(g_w   + (size_t)(row0+lr)*64 + k0+lk);
        float4 b4 = *(const float4*)(g_pfc + (size_t)(col0+lr)*64 + k0+lk);
        As[lk+0][lr]=a4.x; As[lk+1][lr]=a4.y; As[lk+2][lr]=a4.z; As[lk+3][lr]=a4.w;
        Bs[lk+0][lr]=b4.x; Bs[lk+1][lr]=b4.y; Bs[lk+2][lr]=b4.z; Bs[lk+3][lr]=b4.w;
        __syncthreads();
#pragma unroll
        for (int kk = 0; kk < 8; kk++) {
            float ar[8], br[8];
            *(float4*)(ar)   = *(const float4*)&As[kk][ty*8];
            *(float4*)(ar+4) = *(const float4*)&As[kk][ty*8+4];
            *(float4*)(br)   = *(const float4*)&Bs[kk][tx*8];
            *(float4*)(br+4) = *(const float4*)&Bs[kk][tx*8+4];
#pragma unroll
            for (int i = 0; i < 8; i++)
#pragma unroll
                for (int j = 0; j < 8; j++) acc[i][j] += ar[i]*br[j];
        }
        __syncthreads();
    }

#pragma unroll
    for (int i = 0; i < 8; i++) {
        const int r = row0 + ty*8 + i;
#pragma unroll
        for (int j = 0; j < 8; j++) {
            const int c = col0 + tx*8 + j;
            out[(size_t)r*512 + c] = acc[i][j] + g_pbias[c];
        }
    }
}

extern "C" void kernel_launch(void* const* d_in, const int* in_sizes, int n_in,
                              void* d_out, int out_size)
{
    const float* node   = (const float*)d_in[0];
    const float* edge   = (const float*)d_in[1];
    const unsigned char* mask = (const unsigned char*)d_in[2];
    const float* qkv_w  = (const float*)d_in[3];
    const float* qkv_b  = (const float*)d_in[4];
    const float* red_w  = (const float*)d_in[5];
    const float* red_b  = (const float*)d_in[6];
    const float* exp_w  = (const float*)d_in[7];
    const float* exp_b  = (const float*)d_in[8];
    const float* fc_w   = (const float*)d_in[9];
    const float* fc_b   = (const float*)d_in[10];
    const float* proj_w = (const float*)d_in[11];
    const float* proj_b = (const float*)d_in[12];

    float* node_out = (float*)d_out;
    float* edge_out = (float*)d_out + (size_t)B_*N_*C_;

    qkv_gemm_kernel<<<dim3(12, 32), 256>>>(node, qkv_w, qkv_b);
    pfc_kernel<<<512, 64>>>(proj_w, fc_w, fc_b, proj_b);

    const int smemB = SMEM_FLOATS * 4;
    cudaFuncSetAttribute(fused_attn_kernel, cudaFuncAttributeMaxDynamicSharedMemorySize, smemB);
    fused_attn_kernel<<<dim3(N_/4, B_), 512, smemB>>>(edge, mask, red_w, red_b,
                                                      exp_w, exp_b, edge_out);

    out_gemm_kernel<<<dim3(4, 32), 256>>>(proj_w, node_out);
}